// round 15
// baseline (speedup 1.0000x reference)
#include <cuda_runtime.h>
#include <cuda_fp16.h>
#include <math.h>
#include <stdint.h>

#define BATCH 32768
#define HID   2048

// ---------------------------------------------------------------------------
// Device scratch (allocations forbidden -> __device__ globals)
// ---------------------------------------------------------------------------
__device__ __align__(1024) __half g_h1[(size_t)BATCH * HID];
__device__ __align__(1024) __half g_w2[(size_t)HID * HID];   // [K][N] same layout as W2

// ---------------------------------------------------------------------------
// PTX helpers (arch-agnostic: sm_75+/sm_80+ features only)
// ---------------------------------------------------------------------------
__device__ __forceinline__ uint32_t smem_to_u32(const void* p) {
    uint32_t a;
    asm("{ .reg .u64 t; cvta.to.shared.u64 t, %1; cvt.u32.u64 %0, t; }" : "=r"(a) : "l"(p));
    return a;
}
__device__ __forceinline__ float tanh_fast(float x) {   // HW tanh (MUFU), sm_75+
    float y;
    asm("tanh.approx.f32 %0, %1;" : "=f"(y) : "f"(x));
    return y;
}
__device__ __forceinline__ void ldsm4(uint32_t* r, uint32_t addr) {
    asm volatile("ldmatrix.sync.aligned.m8n8.x4.shared.b16 {%0,%1,%2,%3}, [%4];"
        : "=r"(r[0]), "=r"(r[1]), "=r"(r[2]), "=r"(r[3]) : "r"(addr));
}
__device__ __forceinline__ void ldsm4t(uint32_t* r, uint32_t addr) {
    asm volatile("ldmatrix.sync.aligned.m8n8.x4.trans.shared.b16 {%0,%1,%2,%3}, [%4];"
        : "=r"(r[0]), "=r"(r[1]), "=r"(r[2]), "=r"(r[3]) : "r"(addr));
}
__device__ __forceinline__ void mma16816(float* d, const uint32_t* a, const uint32_t* b) {
    asm volatile("mma.sync.aligned.m16n8k16.row.col.f32.f16.f16.f32 "
        "{%0,%1,%2,%3}, {%4,%5,%6,%7}, {%8,%9}, {%0,%1,%2,%3};"
        : "+f"(d[0]), "+f"(d[1]), "+f"(d[2]), "+f"(d[3])
        : "r"(a[0]), "r"(a[1]), "r"(a[2]), "r"(a[3]), "r"(b[0]), "r"(b[1]));
}
__device__ __forceinline__ void cpasync16(uint32_t dst, const void* src) {
    asm volatile("cp.async.cg.shared.global [%0], [%1], 16;" :: "r"(dst), "l"(src));
}
#define CP_COMMIT() asm volatile("cp.async.commit_group;" ::: "memory")
#define CP_WAIT1()  asm volatile("cp.async.wait_group 1;" ::: "memory")

// ---------------------------------------------------------------------------
// Fused prep kernel (independent work, one launch):
//   blocks [0, 4096):        W2 fp32->fp16 conversion (+ out[i]=bc[0] init)
//   blocks [4096, 6144):     layer 1 (16 batch rows per block, HW tanh/cos)
//   blocks [6144, 6272):     risk head (exact tanhf)
// ---------------------------------------------------------------------------
#define L1_ROWS 16
#define NB_W2   ((HID * HID) / 1024)          // 4096
#define NB_L1   (BATCH / L1_ROWS)             // 2048
#define NB_RISK (BATCH / 256)                 // 128

__global__ void __launch_bounds__(256)
prep_kernel(const float* __restrict__ W2,
            const float* __restrict__ bc,
            const float* __restrict__ x,
            const float* __restrict__ W1,
            const float* __restrict__ b1,
            const float* __restrict__ Wr1, const float* __restrict__ br1,
            const float* __restrict__ Wr2, const float* __restrict__ br2,
            const float* __restrict__ Wr3, const float* __restrict__ br3,
            float* __restrict__ out) {
    const int blk = blockIdx.x;

    if (blk < NB_W2) {
        int gi = blk * 256 + threadIdx.x;
        if (gi < BATCH) out[gi] = bc[0];
        size_t i = (size_t)gi * 4;
        float4 v = *(const float4*)(W2 + i);
        __half2* d = (__half2*)(g_w2 + i);
        d[0] = __floats2half2_rn(v.x, v.y);
        d[1] = __floats2half2_rn(v.z, v.w);
        return;
    }

    if (blk < NB_W2 + NB_L1) {
        const int b0 = (blk - NB_W2) * L1_ROWS;
        const int k = threadIdx.x * 8;

        __shared__ float xs[2 * L1_ROWS];
        if (threadIdx.x < 2 * L1_ROWS) xs[threadIdx.x] = x[2 * b0 + threadIdx.x];

        float4 w0a = *(const float4*)(W1 + 0 * HID + k), w0b = *(const float4*)(W1 + 0 * HID + k + 4);
        float4 w1a = *(const float4*)(W1 + 1 * HID + k), w1b = *(const float4*)(W1 + 1 * HID + k + 4);
        float4 w2a = *(const float4*)(W1 + 2 * HID + k), w2b = *(const float4*)(W1 + 2 * HID + k + 4);
        float4 w3a = *(const float4*)(W1 + 3 * HID + k), w3b = *(const float4*)(W1 + 3 * HID + k + 4);
        float4 w4a = *(const float4*)(W1 + 4 * HID + k), w4b = *(const float4*)(W1 + 4 * HID + k + 4);
        float4 w5a = *(const float4*)(W1 + 5 * HID + k), w5b = *(const float4*)(W1 + 5 * HID + k + 4);
        float4 bba = *(const float4*)(b1 + k),           bbb = *(const float4*)(b1 + k + 4);
        float cc[8] = { w4a.x + w5a.x + bba.x, w4a.y + w5a.y + bba.y,
                        w4a.z + w5a.z + bba.z, w4a.w + w5a.w + bba.w,
                        w4b.x + w5b.x + bbb.x, w4b.y + w5b.y + bbb.y,
                        w4b.z + w5b.z + bbb.z, w4b.w + w5b.w + bbb.w };
        float wa[8]  = { w0a.x, w0a.y, w0a.z, w0a.w, w0b.x, w0b.y, w0b.z, w0b.w };
        float wb[8]  = { w1a.x, w1a.y, w1a.z, w1a.w, w1b.x, w1b.y, w1b.z, w1b.w };
        float wq0[8] = { w2a.x, w2a.y, w2a.z, w2a.w, w2b.x, w2b.y, w2b.z, w2b.w };
        float wq1[8] = { w3a.x, w3a.y, w3a.z, w3a.w, w3b.x, w3b.y, w3b.z, w3b.w };
        __syncthreads();

        #pragma unroll
        for (int r = 0; r < L1_ROWS; r++) {
            float x0 = xs[2 * r], x1 = xs[2 * r + 1];
            float c0 = __cosf(x0), c01 = c0 * __cosf(x1);
            __half2 hv[4];
            #pragma unroll
            for (int p = 0; p < 4; p++) {
                float v0 = tanh_fast(x0 * wa[2*p]   + x1 * wb[2*p]   + c0 * wq0[2*p]   + c01 * wq1[2*p]   + cc[2*p]);
                float v1 = tanh_fast(x0 * wa[2*p+1] + x1 * wb[2*p+1] + c0 * wq0[2*p+1] + c01 * wq1[2*p+1] + cc[2*p+1]);
                hv[p] = __floats2half2_rn(v0, v1);
            }
            *(uint4*)(g_h1 + (size_t)(b0 + r) * HID + k) = *(uint4*)hv;
        }
        return;
    }

    // ---- risk head (2->8->4->1), exact tanhf ----
    {
        int b = (blk - NB_W2 - NB_L1) * 256 + threadIdx.x;
        float x0 = x[2 * b], x1 = x[2 * b + 1];
        float r1[8];
        #pragma unroll
        for (int j = 0; j < 8; j++)
            r1[j] = tanhf(x0 * Wr1[j] + x1 * Wr1[8 + j] + br1[j]);
        float r2[4];
        #pragma unroll
        for (int m = 0; m < 4; m++) {
            float s = br2[m];
            #pragma unroll
            for (int j = 0; j < 8; j++) s += r1[j] * Wr2[j * 4 + m];
            r2[m] = tanhf(s);
        }
        float risk = br3[0];
        #pragma unroll
        for (int m = 0; m < 4; m++) risk += r2[m] * Wr3[m];
        out[BATCH + b] = risk;
    }
}

// ---------------------------------------------------------------------------
// Persistent GEMM2 via mma.sync fp16, fused epilogue:
//   h2 = tanh(h1 @ W2 + b2); out[m] += sum_n h2[m,n] * Wc[n]
// 296 persistent CTAs, each ~14 tiles of 128x128; the 3-stage cp.async ring
// rolls continuously across tile boundaries (boundary iterations prefetch the
// next tile's first chunks). Tile 128x128x64, 2x4 warps, 64x32/warp, 2 CTAs/SM.
// ---------------------------------------------------------------------------
#define BM 128
#define BN 128
#define BKQ 64
#define NIT (HID / BKQ)        // 32
#define LDA 72                 // 64 + 8 pad (fp16 elements)
#define LDB 136                // 128 + 8 pad
#define A_BYTES (BM * LDA * 2)     // 18432
#define B_BYTES (BKQ * LDB * 2)    // 17408
#define ST_BYTES (A_BYTES + B_BYTES)           // 35840
#define NSTAGE 3
#define GEMM_SMEM (NSTAGE * ST_BYTES)          // 107520

#define NCTA   296             // 2 per SM x 148 SMs
#define NTILES ((BATCH / BM) * (HID / BN))     // 4096; tile: n = t & 15, m = t >> 4

// per-ks constant strides
#define A_G_KS ((size_t)32 * HID * 2)   // 32 rows of A in gmem (bytes)
#define B_G_KS ((size_t)16 * HID * 2)   // 16 k-rows of B in gmem (bytes)
#define A_S_KS (32 * LDA * 2)           // 32 rows of A in smem (bytes)
#define B_S_KS (16 * LDB * 2)           // 16 k-rows of B in smem (bytes)

__global__ void __launch_bounds__(256, 2)
gemm2_mma_kernel(const float* __restrict__ b2,
                 const float* __restrict__ Wc,
                 float* __restrict__ out) {
    extern __shared__ __align__(16) char smem[];
    const int tid = threadIdx.x;
    const int lane = tid & 31;
    const int wid = tid >> 5;
    const int warp_m = wid >> 2;     // 0..1
    const int warp_n = wid & 3;      // 0..3
    const uint32_t smb = smem_to_u32(smem);

    // per-thread loader positions
    const int ar = tid >> 3, asc = (tid & 7) * 8;     // A: row, k-elem
    const int bkr = tid >> 4, bnc = (tid & 15) * 8;   // B: k-row, n-elem
    const uint32_t aSoff = (ar * LDA + asc) * 2;
    const uint32_t bSoff = A_BYTES + (bkr * LDB + bnc) * 2;

    // per-warp ldsm base offsets (within stage)
    const uint32_t aLbase = ((warp_m * 64 + (lane & 15)) * LDA + (lane >> 4) * 8) * 2;
    const uint32_t bLbase = A_BYTES + ((lane & 15) * LDB + warp_n * 32 + (lane >> 4) * 8) * 2;

    const int my_nt = (NTILES - blockIdx.x + (NCTA - 1)) / NCTA;

    // ---- prime ring: chunks 0,1 of first tile ----
    {
        const int t0 = blockIdx.x;
        const int row0 = (t0 >> 4) * BM, n0 = (t0 & 15) * BN;
        #pragma unroll
        for (int pre = 0; pre < 2; pre++) {
            const uint32_t st = smb + pre * ST_BYTES;
            const char* ag = (const char*)(g_h1 + (size_t)(row0 + ar) * HID + pre * BKQ + asc);
            const char* bg = (const char*)(g_w2 + (size_t)(pre * BKQ + bkr) * HID + n0 + bnc);
            #pragma unroll
            for (int l = 0; l < 4; l++) {
                cpasync16(st + aSoff + l * A_S_KS, ag + l * A_G_KS);
                cpasync16(st + bSoff + l * B_S_KS, bg + l * B_G_KS);
            }
            CP_COMMIT();
        }
    }

    // rolling stage cursors: compute at stage 0, prefetch at stage 2
    uint32_t st_c = smb;
    uint32_t st_p = smb + 2 * ST_BYTES;
    const uint32_t smb_end = smb + 3 * ST_BYTES;

    for (int tt = 0; tt < my_nt; tt++) {
        const int tile = blockIdx.x + tt * NCTA;
        const int row0 = (tile >> 4) * BM, n0 = (tile & 15) * BN;
        const bool have_next = (tile + NCTA < NTILES);

        float acc[4][4][4];
        #pragma unroll
        for (int mt = 0; mt < 4; mt++)
            #pragma unroll
            for (int nt = 0; nt < 4; nt++)
                #pragma unroll
                for (int e = 0; e < 4; e++)
                    acc[mt][nt][e] = 0.f;

        // running prefetch pointers for this tile's chunks 2..31
        const char* agp = (const char*)(g_h1 + (size_t)(row0 + ar) * HID + 2 * BKQ + asc);
        const char* bgp = (const char*)(g_w2 + (size_t)(2 * BKQ + bkr) * HID + n0 + bnc);

        for (int it = 0; it < NIT; it++) {
            CP_WAIT1();
            __syncthreads();   // stage ready; all warps done with stage (flat-1)%3

            const bool pf_local = (it < NIT - 2);

            // boundary iterations: prefetch next tile's chunk (it - 30)
            if (!pf_local && have_next) {
                const int tn = tile + NCTA;
                const int nrow0 = (tn >> 4) * BM, nn0 = (tn & 15) * BN;
                const int k0 = (it - (NIT - 2)) * BKQ;
                const char* ag = (const char*)(g_h1 + (size_t)(nrow0 + ar) * HID + k0 + asc);
                const char* bg = (const char*)(g_w2 + (size_t)(k0 + bkr) * HID + nn0 + bnc);
                #pragma unroll
                for (int l = 0; l < 4; l++) {
                    cpasync16(st_p + aSoff + l * A_S_KS, ag + l * A_G_KS);
                    cpasync16(st_p + bSoff + l * B_S_KS, bg + l * B_G_KS);
                }
            }

            #pragma unroll
            for (int ks = 0; ks < 4; ks++) {
                uint32_t a[4][4], b[4][2];
                #pragma unroll
                for (int mt = 0; mt < 4; mt++)
                    ldsm4(a[mt], st_c + aLbase + (mt * 16 * LDA + ks * 16) * 2);
                #pragma unroll
                for (int ng = 0; ng < 2; ng++) {
                    uint32_t t[4];
                    ldsm4t(t, st_c + bLbase + (ks * 16 * LDB + ng * 16) * 2);
                    b[2*ng][0] = t[0]; b[2*ng][1] = t[1];
                    b[2*ng+1][0] = t[2]; b[2*ng+1][1] = t[3];
                }
                // interleaved prefetch slice for in-tile chunks
                if (pf_local) {
                    cpasync16(st_p + aSoff + ks * A_S_KS, agp + ks * A_G_KS);
                    cpasync16(st_p + bSoff + ks * B_S_KS, bgp + ks * B_G_KS);
                }
                #pragma unroll
                for (int mt = 0; mt < 4; mt++)
                    #pragma unroll
                    for (int nt = 0; nt < 4; nt++)
                        mma16816(acc[mt][nt], a[mt], b[nt]);
            }
            CP_COMMIT();   // exactly one group per iteration (empty on drained tail)

            agp += BKQ * 2;                 // +128 bytes
            bgp += (size_t)BKQ * HID * 2;   // +256 KiB
            st_c += ST_BYTES; if (st_c == smb_end) st_c = smb;
            st_p += ST_BYTES; if (st_p == smb_end) st_p = smb;
        }

        // ---- per-tile fused epilogue (no smem: overlaps in-flight prefetch) ----
        const int r = lane >> 2, cq = lane & 3;
        #pragma unroll
        for (int mt = 0; mt < 4; mt++) {
            float p0 = 0.f, p1 = 0.f;
            #pragma unroll
            for (int nt = 0; nt < 4; nt++) {
                int c = n0 + warp_n * 32 + nt * 8 + cq * 2;
                float w0 = __ldg(Wc + c), w1 = __ldg(Wc + c + 1);
                float bb0 = __ldg(b2 + c), bb1 = __ldg(b2 + c + 1);
                p0 += tanh_fast(acc[mt][nt][0] + bb0) * w0 + tanh_fast(acc[mt][nt][1] + bb1) * w1;
                p1 += tanh_fast(acc[mt][nt][2] + bb0) * w0 + tanh_fast(acc[mt][nt][3] + bb1) * w1;
            }
            p0 += __shfl_xor_sync(0xffffffffu, p0, 1);
            p0 += __shfl_xor_sync(0xffffffffu, p0, 2);
            p1 += __shfl_xor_sync(0xffffffffu, p1, 1);
            p1 += __shfl_xor_sync(0xffffffffu, p1, 2);
            if (cq == 0) {
                int grow = row0 + warp_m * 64 + mt * 16 + r;
                atomicAdd(out + grow, p0);
                atomicAdd(out + grow + 8, p1);
            }
        }
    }
}

// ---------------------------------------------------------------------------
extern "C" void kernel_launch(void* const* d_in, const int* in_sizes, int n_in,
                              void* d_out, int out_size) {
    const float* x   = (const float*)d_in[0];
    const float* W1  = (const float*)d_in[1];
    const float* b1  = (const float*)d_in[2];
    const float* W2  = (const float*)d_in[3];
    const float* b2  = (const float*)d_in[4];
    const float* Wc  = (const float*)d_in[5];
    const float* bc  = (const float*)d_in[6];
    const float* Wr1 = (const float*)d_in[7];
    const float* br1 = (const float*)d_in[8];
    const float* Wr2 = (const float*)d_in[9];
    const float* br2 = (const float*)d_in[10];
    const float* Wr3 = (const float*)d_in[11];
    const float* br3 = (const float*)d_in[12];
    float* out = (float*)d_out;

    static bool attr_set = false;
    if (!attr_set) {
        cudaFuncSetAttribute(gemm2_mma_kernel,
                             cudaFuncAttributeMaxDynamicSharedMemorySize, GEMM_SMEM);
        attr_set = true;
    }

    prep_kernel<<<NB_W2 + NB_L1 + NB_RISK, 256>>>(W2, bc, x, W1, b1,
                                                  Wr1, br1, Wr2, br2, Wr3, br3, out);
    gemm2_mma_kernel<<<NCTA, 256, GEMM_SMEM>>>(b2, Wc, out);
}

// round 16
// speedup vs baseline: 1.1217x; 1.1217x over previous
#include <cuda_runtime.h>
#include <cuda_fp16.h>
#include <math.h>
#include <stdint.h>

#define BATCH 32768
#define HID   2048

// ---------------------------------------------------------------------------
// Device scratch (allocations forbidden -> __device__ globals)
// ---------------------------------------------------------------------------
__device__ __align__(1024) __half g_h1[(size_t)BATCH * HID];
__device__ __align__(1024) __half g_w2[(size_t)HID * HID];   // [K][N] same layout as W2

// ---------------------------------------------------------------------------
// PTX helpers (arch-agnostic: sm_75+/sm_80+ features only)
// ---------------------------------------------------------------------------
__device__ __forceinline__ uint32_t smem_to_u32(const void* p) {
    uint32_t a;
    asm("{ .reg .u64 t; cvta.to.shared.u64 t, %1; cvt.u32.u64 %0, t; }" : "=r"(a) : "l"(p));
    return a;
}
__device__ __forceinline__ float tanh_fast(float x) {   // HW tanh (MUFU), sm_75+
    float y;
    asm("tanh.approx.f32 %0, %1;" : "=f"(y) : "f"(x));
    return y;
}
__device__ __forceinline__ void ldsm4(uint32_t* r, uint32_t addr) {
    asm volatile("ldmatrix.sync.aligned.m8n8.x4.shared.b16 {%0,%1,%2,%3}, [%4];"
        : "=r"(r[0]), "=r"(r[1]), "=r"(r[2]), "=r"(r[3]) : "r"(addr));
}
__device__ __forceinline__ void ldsm4t(uint32_t* r, uint32_t addr) {
    asm volatile("ldmatrix.sync.aligned.m8n8.x4.trans.shared.b16 {%0,%1,%2,%3}, [%4];"
        : "=r"(r[0]), "=r"(r[1]), "=r"(r[2]), "=r"(r[3]) : "r"(addr));
}
__device__ __forceinline__ void mma16816(float* d, const uint32_t* a, const uint32_t* b) {
    asm volatile("mma.sync.aligned.m16n8k16.row.col.f32.f16.f16.f32 "
        "{%0,%1,%2,%3}, {%4,%5,%6,%7}, {%8,%9}, {%0,%1,%2,%3};"
        : "+f"(d[0]), "+f"(d[1]), "+f"(d[2]), "+f"(d[3])
        : "r"(a[0]), "r"(a[1]), "r"(a[2]), "r"(a[3]), "r"(b[0]), "r"(b[1]));
}
__device__ __forceinline__ void cpasync16(uint32_t dst, const void* src) {
    asm volatile("cp.async.cg.shared.global [%0], [%1], 16;" :: "r"(dst), "l"(src));
}
#define CP_COMMIT() asm volatile("cp.async.commit_group;" ::: "memory")
#define CP_WAIT1()  asm volatile("cp.async.wait_group 1;" ::: "memory")

// ---------------------------------------------------------------------------
// Fused prep kernel (independent work, one launch):
//   blocks [0, 2048):        W2 fp32->fp16 conversion, 8 floats/thread
//                            (+ out[i]=bc[0] init, first 128 blocks' range)
//   blocks [2048, 4096):     layer 1 (16 batch rows per block, HW tanh/cos)
//   blocks [4096, 4224):     risk head (exact tanhf)
// ---------------------------------------------------------------------------
#define L1_ROWS 16
#define NB_W2   ((HID * HID) / 2048)          // 2048 (8 floats per thread)
#define NB_L1   (BATCH / L1_ROWS)             // 2048
#define NB_RISK (BATCH / 256)                 // 128

__global__ void __launch_bounds__(256)
prep_kernel(const float* __restrict__ W2,
            const float* __restrict__ bc,
            const float* __restrict__ x,
            const float* __restrict__ W1,
            const float* __restrict__ b1,
            const float* __restrict__ Wr1, const float* __restrict__ br1,
            const float* __restrict__ Wr2, const float* __restrict__ br2,
            const float* __restrict__ Wr3, const float* __restrict__ br3,
            float* __restrict__ out) {
    const int blk = blockIdx.x;

    if (blk < NB_W2) {
        // ---- W2 conversion (8 floats/thread) + logits-bias init ----
        int gi = blk * 256 + threadIdx.x;
        if (gi < BATCH) out[gi] = bc[0];
        size_t i = (size_t)gi * 8;
        float4 v0 = *(const float4*)(W2 + i);
        float4 v1 = *(const float4*)(W2 + i + 4);
        __half2* d = (__half2*)(g_w2 + i);
        d[0] = __floats2half2_rn(v0.x, v0.y);
        d[1] = __floats2half2_rn(v0.z, v0.w);
        d[2] = __floats2half2_rn(v1.x, v1.y);
        d[3] = __floats2half2_rn(v1.z, v1.w);
        return;
    }

    if (blk < NB_W2 + NB_L1) {
        // ---- layer 1: closed-form quantum features, HW tanh/cos, fp16 h1 ----
        const int b0 = (blk - NB_W2) * L1_ROWS;
        const int k = threadIdx.x * 8;

        __shared__ float xs[2 * L1_ROWS];
        if (threadIdx.x < 2 * L1_ROWS) xs[threadIdx.x] = x[2 * b0 + threadIdx.x];

        float4 w0a = *(const float4*)(W1 + 0 * HID + k), w0b = *(const float4*)(W1 + 0 * HID + k + 4);
        float4 w1a = *(const float4*)(W1 + 1 * HID + k), w1b = *(const float4*)(W1 + 1 * HID + k + 4);
        float4 w2a = *(const float4*)(W1 + 2 * HID + k), w2b = *(const float4*)(W1 + 2 * HID + k + 4);
        float4 w3a = *(const float4*)(W1 + 3 * HID + k), w3b = *(const float4*)(W1 + 3 * HID + k + 4);
        float4 w4a = *(const float4*)(W1 + 4 * HID + k), w4b = *(const float4*)(W1 + 4 * HID + k + 4);
        float4 w5a = *(const float4*)(W1 + 5 * HID + k), w5b = *(const float4*)(W1 + 5 * HID + k + 4);
        float4 bba = *(const float4*)(b1 + k),           bbb = *(const float4*)(b1 + k + 4);
        float cc[8] = { w4a.x + w5a.x + bba.x, w4a.y + w5a.y + bba.y,
                        w4a.z + w5a.z + bba.z, w4a.w + w5a.w + bba.w,
                        w4b.x + w5b.x + bbb.x, w4b.y + w5b.y + bbb.y,
                        w4b.z + w5b.z + bbb.z, w4b.w + w5b.w + bbb.w };
        float wa[8]  = { w0a.x, w0a.y, w0a.z, w0a.w, w0b.x, w0b.y, w0b.z, w0b.w };
        float wb[8]  = { w1a.x, w1a.y, w1a.z, w1a.w, w1b.x, w1b.y, w1b.z, w1b.w };
        float wq0[8] = { w2a.x, w2a.y, w2a.z, w2a.w, w2b.x, w2b.y, w2b.z, w2b.w };
        float wq1[8] = { w3a.x, w3a.y, w3a.z, w3a.w, w3b.x, w3b.y, w3b.z, w3b.w };
        __syncthreads();

        #pragma unroll
        for (int r = 0; r < L1_ROWS; r++) {
            float x0 = xs[2 * r], x1 = xs[2 * r + 1];
            float c0 = __cosf(x0), c01 = c0 * __cosf(x1);
            __half2 hv[4];
            #pragma unroll
            for (int p = 0; p < 4; p++) {
                float v0 = tanh_fast(x0 * wa[2*p]   + x1 * wb[2*p]   + c0 * wq0[2*p]   + c01 * wq1[2*p]   + cc[2*p]);
                float v1 = tanh_fast(x0 * wa[2*p+1] + x1 * wb[2*p+1] + c0 * wq0[2*p+1] + c01 * wq1[2*p+1] + cc[2*p+1]);
                hv[p] = __floats2half2_rn(v0, v1);
            }
            *(uint4*)(g_h1 + (size_t)(b0 + r) * HID + k) = *(uint4*)hv;
        }
        return;
    }

    // ---- risk head (2->8->4->1), exact tanhf ----
    {
        int b = (blk - NB_W2 - NB_L1) * 256 + threadIdx.x;
        float x0 = x[2 * b], x1 = x[2 * b + 1];
        float r1[8];
        #pragma unroll
        for (int j = 0; j < 8; j++)
            r1[j] = tanhf(x0 * Wr1[j] + x1 * Wr1[8 + j] + br1[j]);
        float r2[4];
        #pragma unroll
        for (int m = 0; m < 4; m++) {
            float s = br2[m];
            #pragma unroll
            for (int j = 0; j < 8; j++) s += r1[j] * Wr2[j * 4 + m];
            r2[m] = tanhf(s);
        }
        float risk = br3[0];
        #pragma unroll
        for (int m = 0; m < 4; m++) risk += r2[m] * Wr3[m];
        out[BATCH + b] = risk;
    }
}

// ---------------------------------------------------------------------------
// GEMM2 via mma.sync fp16 single-pass, fused epilogue:  (R13 config, proven)
//   h2 = tanh(h1 @ W2 + b2); out[m] += sum_n h2[m,n] * Wc[n]
// Tile 128x128x64, 256 threads (2x4 warps, 64x32 per warp), 3-stage cp.async,
// one barrier per iteration, 2 CTAs/SM. Prefetch interleaved into ks-groups.
// ---------------------------------------------------------------------------
#define BM 128
#define BN 128
#define BKQ 64
#define NIT (HID / BKQ)        // 32
#define LDA 72                 // 64 + 8 pad (fp16 elements)
#define LDB 136                // 128 + 8 pad
#define A_BYTES (BM * LDA * 2)     // 18432
#define B_BYTES (BKQ * LDB * 2)    // 17408
#define ST_BYTES (A_BYTES + B_BYTES)           // 35840
#define NSTAGE 3
#define GEMM_SMEM (NSTAGE * ST_BYTES)          // 107520

// per-ks constant strides
#define A_G_KS ((size_t)32 * HID * 2)   // 32 rows of A in gmem (bytes)
#define B_G_KS ((size_t)16 * HID * 2)   // 16 k-rows of B in gmem (bytes)
#define A_S_KS (32 * LDA * 2)           // 32 rows of A in smem (bytes)
#define B_S_KS (16 * LDB * 2)           // 16 k-rows of B in smem (bytes)

__global__ void __launch_bounds__(256, 2)
gemm2_mma_kernel(const float* __restrict__ b2,
                 const float* __restrict__ Wc,
                 float* __restrict__ out) {
    extern __shared__ __align__(16) char smem[];
    const int tid = threadIdx.x;
    const int lane = tid & 31;
    const int wid = tid >> 5;
    const int warp_m = wid >> 2;     // 0..1
    const int warp_n = wid & 3;      // 0..3
    const int row0 = blockIdx.y * BM;
    const int n0 = blockIdx.x * BN;
    const uint32_t smb = smem_to_u32(smem);

    float acc[4][4][4];
    #pragma unroll
    for (int mt = 0; mt < 4; mt++)
        #pragma unroll
        for (int nt = 0; nt < 4; nt++)
            #pragma unroll
            for (int e = 0; e < 4; e++)
                acc[mt][nt][e] = 0.f;

    // per-thread base positions (ks offsets are the constants above)
    const int ar = tid >> 3, asc = (tid & 7) * 8;     // A: row, k-elem
    const int bkr = tid >> 4, bnc = (tid & 15) * 8;   // B: k-row, n-elem
    const uint32_t aSoff = (ar * LDA + asc) * 2;      // smem offsets within stage
    const uint32_t bSoff = A_BYTES + (bkr * LDB + bnc) * 2;

    // ---- prefetch stages 0,1 ----
    #pragma unroll
    for (int pre = 0; pre < 2; pre++) {
        const int k0 = pre * BKQ;
        const uint32_t st = smb + pre * ST_BYTES;
        const char* ag = (const char*)(g_h1 + (size_t)(row0 + ar) * HID + k0 + asc);
        const char* bg = (const char*)(g_w2 + (size_t)(k0 + bkr) * HID + n0 + bnc);
        #pragma unroll
        for (int l = 0; l < 4; l++) {
            cpasync16(st + aSoff + l * A_S_KS, ag + l * A_G_KS);
            cpasync16(st + bSoff + l * B_S_KS, bg + l * B_G_KS);
        }
        CP_COMMIT();
    }

    // running prefetch pointers (stage 2 onward); advance by BKQ per iteration
    const char* agp = (const char*)(g_h1 + (size_t)(row0 + ar) * HID + 2 * BKQ + asc);
    const char* bgp = (const char*)(g_w2 + (size_t)(2 * BKQ + bkr) * HID + n0 + bnc);

    // cycling stage bases: compute starts at stage 0, prefetch at stage 2
    uint32_t st_c = smb;
    uint32_t st_p = smb + 2 * ST_BYTES;
    const uint32_t smb_end = smb + 3 * ST_BYTES;

    // per-warp ldsm base offsets (within stage)
    const uint32_t aLbase = ((warp_m * 64 + (lane & 15)) * LDA + (lane >> 4) * 8) * 2;
    const uint32_t bLbase = A_BYTES + ((lane & 15) * LDB + warp_n * 32 + (lane >> 4) * 8) * 2;

    for (int it = 0; it < NIT; it++) {
        CP_WAIT1();
        __syncthreads();   // stage `it` visible; all warps done with stage (it-1)%3

        const bool do_pf = (it + 2 < NIT);

        #pragma unroll
        for (int ks = 0; ks < 4; ks++) {
            uint32_t a[4][4], b[4][2];
            #pragma unroll
            for (int mt = 0; mt < 4; mt++)
                ldsm4(a[mt], st_c + aLbase + (mt * 16 * LDA + ks * 16) * 2);
            #pragma unroll
            for (int ng = 0; ng < 2; ng++) {
                uint32_t t[4];
                ldsm4t(t, st_c + bLbase + (ks * 16 * LDB + ng * 16) * 2);
                b[2*ng][0] = t[0]; b[2*ng][1] = t[1];
                b[2*ng+1][0] = t[2]; b[2*ng+1][1] = t[3];
            }
            // interleaved prefetch slice (immediates for per-ks strides)
            if (do_pf) {
                cpasync16(st_p + aSoff + ks * A_S_KS, agp + ks * A_G_KS);
                cpasync16(st_p + bSoff + ks * B_S_KS, bgp + ks * B_G_KS);
            }
            #pragma unroll
            for (int mt = 0; mt < 4; mt++)
                #pragma unroll
                for (int nt = 0; nt < 4; nt++)
                    mma16816(acc[mt][nt], a[mt], b[nt]);
        }
        CP_COMMIT();

        // advance running pointers / cycle stage bases (no div/mod)
        agp += BKQ * 2;                 // +128 bytes
        bgp += (size_t)BKQ * HID * 2;   // +256 KiB
        st_c += ST_BYTES; if (st_c == smb_end) st_c = smb;
        st_p += ST_BYTES; if (st_p == smb_end) st_p = smb;
    }

    // ---- fused epilogue: HW tanh + b2, dot with Wc, quad-reduce, atomicAdd ----
    const int r = lane >> 2, cq = lane & 3;
    #pragma unroll
    for (int mt = 0; mt < 4; mt++) {
        float p0 = 0.f, p1 = 0.f;
        #pragma unroll
        for (int nt = 0; nt < 4; nt++) {
            int c = n0 + warp_n * 32 + nt * 8 + cq * 2;
            float w0 = __ldg(Wc + c), w1 = __ldg(Wc + c + 1);
            float bb0 = __ldg(b2 + c), bb1 = __ldg(b2 + c + 1);
            p0 += tanh_fast(acc[mt][nt][0] + bb0) * w0 + tanh_fast(acc[mt][nt][1] + bb1) * w1;
            p1 += tanh_fast(acc[mt][nt][2] + bb0) * w0 + tanh_fast(acc[mt][nt][3] + bb1) * w1;
        }
        p0 += __shfl_xor_sync(0xffffffffu, p0, 1);
        p0 += __shfl_xor_sync(0xffffffffu, p0, 2);
        p1 += __shfl_xor_sync(0xffffffffu, p1, 1);
        p1 += __shfl_xor_sync(0xffffffffu, p1, 2);
        if (cq == 0) {
            int grow = row0 + warp_m * 64 + mt * 16 + r;
            atomicAdd(out + grow, p0);
            atomicAdd(out + grow + 8, p1);
        }
    }
}

// ---------------------------------------------------------------------------
extern "C" void kernel_launch(void* const* d_in, const int* in_sizes, int n_in,
                              void* d_out, int out_size) {
    const float* x   = (const float*)d_in[0];
    const float* W1  = (const float*)d_in[1];
    const float* b1  = (const float*)d_in[2];
    const float* W2  = (const float*)d_in[3];
    const float* b2  = (const float*)d_in[4];
    const float* Wc  = (const float*)d_in[5];
    const float* bc  = (const float*)d_in[6];
    const float* Wr1 = (const float*)d_in[7];
    const float* br1 = (const float*)d_in[8];
    const float* Wr2 = (const float*)d_in[9];
    const float* br2 = (const float*)d_in[10];
    const float* Wr3 = (const float*)d_in[11];
    const float* br3 = (const float*)d_in[12];
    float* out = (float*)d_out;

    static bool attr_set = false;
    if (!attr_set) {
        cudaFuncSetAttribute(gemm2_mma_kernel,
                             cudaFuncAttributeMaxDynamicSharedMemorySize, GEMM_SMEM);
        attr_set = true;
    }

    prep_kernel<<<NB_W2 + NB_L1 + NB_RISK, 256>>>(W2, bc, x, W1, b1,
                                                  Wr1, br1, Wr2, br2, Wr3, br3, out);
    // blockIdx.x = n-tile (fastest) so the 16 CTAs sharing an A tile are adjacent
    gemm2_mma_kernel<<<dim3(HID / BN, BATCH / BM), 256, GEMM_SMEM>>>(b2, Wc, out);
}